// round 16
// baseline (speedup 1.0000x reference)
#include <cuda_runtime.h>
#include <cuda_fp16.h>
#include <cstdint>
#include <cstddef>

#define B_ 4
#define S_ 2048
#define D_ 1024
#define H_ 16
#define DK_ 64
#define DFF_ 4096
#define EPS_ 1e-6f
#define NTOK (B_ * S_)          // 8192
#define NBH  (B_ * H_)          // 64
#define QKV_LD (3 * D_)         // fused qkv row stride

// ================= scratch (device globals; no runtime allocation) =================
__device__ __half g_xn_h[(size_t)NTOK * D_];
__device__ __half g_qkv_h[(size_t)NTOK * 3 * D_];     // fused [NTOK, 3*D] = q|k|v
__device__ __half g_attn_h[(size_t)NTOK * D_];
__device__ float  g_x1[(size_t)NTOK * D_];
__device__ __half g_h_h[(size_t)NTOK * DFF_];
// fused transposed fp16 weights
__device__ __half g_wqkvT[(size_t)3 * D_ * D_];       // [3072, 1024] K-major
__device__ float  g_bqkv[3 * D_];
__device__ __half g_woT[(size_t)D_ * D_];
__device__ __half g_w1T[(size_t)DFF_ * D_];
__device__ __half g_w2T[(size_t)D_ * DFF_];

// ================= helpers =================
__device__ __forceinline__ uint32_t smem_u32(const void* p) {
    uint32_t a;
    asm("{ .reg .u64 t; cvta.to.shared.u64 t, %1; cvt.u32.u64 %0, t; }" : "=r"(a) : "l"(p));
    return a;
}
__device__ __forceinline__ void cp_async16(uint32_t smem, const void* g) {
    asm volatile("cp.async.cg.shared.global [%0], [%1], 16;" :: "r"(smem), "l"(g));
}
__device__ __forceinline__ void cp_commit() { asm volatile("cp.async.commit_group;" ::: "memory"); }
template <int N>
__device__ __forceinline__ void cp_wait() { asm volatile("cp.async.wait_group %0;" :: "n"(N) : "memory"); }

__device__ __forceinline__ void ldsm_x4(uint32_t r[4], uint32_t addr) {
    asm volatile("ldmatrix.sync.aligned.m8n8.x4.shared.b16 {%0,%1,%2,%3}, [%4];"
        : "=r"(r[0]), "=r"(r[1]), "=r"(r[2]), "=r"(r[3]) : "r"(addr));
}
__device__ __forceinline__ void ldsm_x4_t(uint32_t r[4], uint32_t addr) {
    asm volatile("ldmatrix.sync.aligned.m8n8.x4.trans.shared.b16 {%0,%1,%2,%3}, [%4];"
        : "=r"(r[0]), "=r"(r[1]), "=r"(r[2]), "=r"(r[3]) : "r"(addr));
}

// fp16 m16n8k16 mma, fp32 accum
__device__ __forceinline__ void mma_f16(float d[4], const uint32_t a[4], const uint32_t b[2]) {
    asm volatile(
        "mma.sync.aligned.m16n8k16.row.col.f32.f16.f16.f32 "
        "{%0,%1,%2,%3}, {%4,%5,%6,%7}, {%8,%9}, {%0,%1,%2,%3};"
        : "+f"(d[0]), "+f"(d[1]), "+f"(d[2]), "+f"(d[3])
        : "r"(a[0]), "r"(a[1]), "r"(a[2]), "r"(a[3]), "r"(b[0]), "r"(b[1]));
}

__device__ __forceinline__ uint32_t packh2(float a, float b) {
    __half2 h = __floats2half2_rn(a, b);
    return *(uint32_t*)&h;
}

// ================= fp16 tensor GEMM: C[M,N] = A[M,K] @ Bt[N,K]^T =================
// BM=256, BN=128, BK=64: 87 FLOP per SMEM-fill byte (vs 64 at 128x128) -> lifts
// the LTS-imposed ceiling from ~67% to ~91% of mma.sync peak. Warp tile 64x64,
// occupancy 1 (acc = 128 regs), 4-stage cp.async pipeline (prefetch distance 3).
#define HG_A_BYTES 32768                 // 256 rows x 128B
#define HG_B_BYTES 16384                 // 128 rows x 128B
#define HG_STAGE_BYTES (HG_A_BYTES + HG_B_BYTES)
#define HG_STAGES 4
#define HG_SMEM_BYTES (HG_STAGES * HG_STAGE_BYTES)   // 196608

template<bool HAS_BIAS, bool RELU, bool HAS_RES, bool OUT_HALF>
__global__ __launch_bounds__(256, 1) void hgemm(
    const __half* __restrict__ A, const __half* __restrict__ Bt,
    const float* __restrict__ bias, const float* __restrict__ res,
    void* __restrict__ Cv, int M, int N, int K, int lda, int ldb, int ldc)
{
    extern __shared__ char smem_raw[];
    const uint32_t sbase = smem_u32(smem_raw);

    const int tid = threadIdx.x, lane = tid & 31, wid = tid >> 5;
    const int wrow = (wid & 3) * 64;           // warp row base (4 row-warps)
    const int wcol = (wid >> 2) * 64;          // warp col base (2 col-warps)
    const int rowBase = blockIdx.y * 256;
    const int colBase = blockIdx.x * 128;

    auto load_chunk = [&](int c) {
        const uint32_t ast = sbase + (uint32_t)(c % HG_STAGES) * HG_STAGE_BYTES;
        const uint32_t bst = ast + HG_A_BYTES;
        const int kOff = c * 64;
        #pragma unroll
        for (int i = 0; i < 8; i++) {               // A: 256 rows x 8 chunks of 16B
            int g = tid + i * 256;
            int r = g >> 3, cc = g & 7;
            cp_async16(ast + r * 128 + (((cc ^ (r & 7))) << 4),
                       A + (size_t)(rowBase + r) * lda + kOff + cc * 8);
        }
        #pragma unroll
        for (int i = 0; i < 4; i++) {               // B: 128 rows x 8 chunks
            int g = tid + i * 256;
            int r = g >> 3, cc = g & 7;
            cp_async16(bst + r * 128 + (((cc ^ (r & 7))) << 4),
                       Bt + (size_t)(colBase + r) * ldb + kOff + cc * 8);
        }
    };

    float acc[4][8][4];
    #pragma unroll
    for (int mt = 0; mt < 4; mt++)
        #pragma unroll
        for (int nt = 0; nt < 8; nt++)
            #pragma unroll
            for (int i = 0; i < 4; i++) acc[mt][nt][i] = 0.f;

    const int NC = K / 64;
    load_chunk(0); cp_commit();
    load_chunk(1); cp_commit();
    load_chunk(2); cp_commit();

    const int arow = wrow + (lane & 15);
    const int ahi  = lane >> 4;
    const int brow = wcol + (lane & 7) + ((lane >> 4) << 3);
    const int bhi  = (lane >> 3) & 1;

    for (int c = 0; c < NC; c++) {
        if (c + 3 < NC) load_chunk(c + 3);
        cp_commit();
        cp_wait<3>();
        __syncthreads();

        const uint32_t ast = sbase + (uint32_t)(c % HG_STAGES) * HG_STAGE_BYTES;
        const uint32_t bst = ast + HG_A_BYTES;

        uint32_t aAddr[4], bAddr[4];
        int arx[4], brx[4];
        #pragma unroll
        for (int mt = 0; mt < 4; mt++) {
            const int r = arow + mt * 16;
            aAddr[mt] = ast + r * 128;
            arx[mt] = r & 7;
        }
        #pragma unroll
        for (int np = 0; np < 4; np++) {
            const int n = brow + np * 16;
            bAddr[np] = bst + n * 128;
            brx[np] = n & 7;
        }

        #pragma unroll
        for (int ks = 0; ks < 4; ks++) {
            uint32_t af[4][4];
            #pragma unroll
            for (int mt = 0; mt < 4; mt++)
                ldsm_x4(af[mt], aAddr[mt] + (((2 * ks + ahi) ^ arx[mt]) << 4));
            #pragma unroll
            for (int np = 0; np < 4; np++) {
                uint32_t bf[4];
                ldsm_x4(bf, bAddr[np] + (((2 * ks + bhi) ^ brx[np]) << 4));
                #pragma unroll
                for (int mt = 0; mt < 4; mt++) {
                    mma_f16(acc[mt][np * 2],     af[mt], bf);
                    mma_f16(acc[mt][np * 2 + 1], af[mt], bf + 2);
                }
            }
        }
        __syncthreads();
    }

    float* Cf = (float*)Cv;
    __half* Ch = (__half*)Cv;
    #pragma unroll
    for (int mt = 0; mt < 4; mt++) {
        const int r0 = rowBase + wrow + mt * 16 + (lane >> 2);
        #pragma unroll
        for (int nt = 0; nt < 8; nt++) {
            const int col = colBase + wcol + nt * 8 + 2 * (lane & 3);
            float vx0 = acc[mt][nt][0], vy0 = acc[mt][nt][1];
            float vx1 = acc[mt][nt][2], vy1 = acc[mt][nt][3];
            if (HAS_BIAS) {
                const float b0v = bias[col], b1v = bias[col + 1];
                vx0 += b0v; vy0 += b1v; vx1 += b0v; vy1 += b1v;
            }
            if (RELU) {
                vx0 = fmaxf(vx0, 0.f); vy0 = fmaxf(vy0, 0.f);
                vx1 = fmaxf(vx1, 0.f); vy1 = fmaxf(vy1, 0.f);
            }
            if (HAS_RES) {
                float2 rv0 = *(const float2*)(res + (size_t)r0 * ldc + col);
                float2 rv1 = *(const float2*)(res + (size_t)(r0 + 8) * ldc + col);
                vx0 += rv0.x; vy0 += rv0.y;
                vx1 += rv1.x; vy1 += rv1.y;
            }
            if (OUT_HALF) {
                *(__half2*)(Ch + (size_t)r0 * ldc + col) = __floats2half2_rn(vx0, vy0);
                *(__half2*)(Ch + (size_t)(r0 + 8) * ldc + col) = __floats2half2_rn(vx1, vy1);
            } else {
                *(float2*)(Cf + (size_t)r0 * ldc + col) = make_float2(vx0, vy0);
                *(float2*)(Cf + (size_t)(r0 + 8) * ldc + col) = make_float2(vx1, vy1);
            }
        }
    }
}

// ================= fp16 flash attention (ldmatrix + register P), fused-QKV input =================
#define OFF_K 16384
#define OFF_V (OFF_K + 2 * 8192)
#define OFF_MSK (OFF_V + 2 * 8192)
#define FA_SMEM_BYTES (OFF_MSK + 2 * 64 * 4)

__global__ __launch_bounds__(256, 2) void flash_h_kernel(
    const __half* __restrict__ qkv, const int* __restrict__ mask,
    __half* __restrict__ attn)
{
    extern __shared__ char smem_raw[];
    float* mskf = (float*)(smem_raw + OFF_MSK);
    const uint32_t sb = smem_u32(smem_raw);

    const int tid = threadIdx.x, lane = tid & 31, wid = tid >> 5;
    const int z = blockIdx.y;
    const int b = z / H_, h = z % H_;
    const int qBase = blockIdx.x * 128;
    const __half* Qg = qkv + (size_t)b * S_ * QKV_LD + h * DK_;
    const __half* Kg = Qg + D_;
    const __half* Vg = Qg + 2 * D_;

    #pragma unroll
    for (int i = 0; i < 4; i++) {
        int g = tid + i * 256;
        int r = g >> 3, cc = g & 7;
        cp_async16(sb + r * 128 + (((cc ^ (r & 7))) << 4),
                   Qg + (size_t)(qBase + r) * QKV_LD + cc * 8);
    }
    cp_commit();

    auto load_tile = [&](int c) {
        const int s = c & 1;
        const int kv0 = c * 64;
        const uint32_t kst = sb + OFF_K + s * 8192;
        const uint32_t vst = sb + OFF_V + s * 8192;
        #pragma unroll
        for (int i = 0; i < 2; i++) {
            int g = tid + i * 256;
            int r = g >> 3, cc = g & 7;
            uint32_t swz = r * 128 + (((cc ^ (r & 7))) << 4);
            cp_async16(kst + swz, Kg + (size_t)(kv0 + r) * QKV_LD + cc * 8);
            cp_async16(vst + swz, Vg + (size_t)(kv0 + r) * QKV_LD + cc * 8);
        }
        if (tid < 64)
            mskf[s * 64 + tid] = (mask[b * S_ + kv0 + tid] == 0) ? -1e30f : 0.0f;
    };

    load_tile(0);
    cp_commit();

    float m0 = -1e30f, m1 = -1e30f, l0 = 0.f, l1 = 0.f;
    float oacc[8][4];
    #pragma unroll
    for (int nt = 0; nt < 8; nt++)
        #pragma unroll
        for (int i = 0; i < 4; i++) oacc[nt][i] = 0.f;

    uint32_t qf[4][4];
    const int wrow = wid * 16;

    const int arow = wrow + (lane & 15);
    const int ahi  = lane >> 4;
    const int krow = (lane & 7) + ((lane >> 4) << 3);
    const int khi  = (lane >> 3) & 1;
    const int vg   = lane >> 3;
    const int vi   = lane & 7;

    const int NKV = S_ / 64;
    for (int c = 0; c < NKV; c++) {
        if (c + 1 < NKV) load_tile(c + 1);
        cp_commit();
        cp_wait<1>();
        __syncthreads();

        if (c == 0) {
            const int arx = arow & 7;
            #pragma unroll
            for (int ks = 0; ks < 4; ks++)
                ldsm_x4(qf[ks], sb + arow * 128 + (((2 * ks + ahi) ^ arx) << 4));
        }

        const uint32_t kst = sb + OFF_K + (c & 1) * 8192;
        const uint32_t vst = sb + OFF_V + (c & 1) * 8192;
        const float* msk = mskf + (c & 1) * 64;

        float sacc[8][4];
        #pragma unroll
        for (int nt = 0; nt < 8; nt++)
            #pragma unroll
            for (int i = 0; i < 4; i++) sacc[nt][i] = 0.f;

        #pragma unroll
        for (int ks = 0; ks < 4; ks++) {
            #pragma unroll
            for (int ng = 0; ng < 4; ng++) {
                const int row = ng * 16 + krow;
                uint32_t bf[4];
                ldsm_x4(bf, kst + row * 128 + (((2 * ks + khi) ^ (row & 7)) << 4));
                mma_f16(sacc[ng * 2],     qf[ks], bf);
                mma_f16(sacc[ng * 2 + 1], qf[ks], bf + 2);
            }
        }

        float tm0 = -1e30f, tm1 = -1e30f;
        #pragma unroll
        for (int nt = 0; nt < 8; nt++) {
            const float ma = msk[nt * 8 + 2 * (lane & 3)];
            const float mb = msk[nt * 8 + 2 * (lane & 3) + 1];
            sacc[nt][0] = sacc[nt][0] * 0.125f + ma;
            sacc[nt][1] = sacc[nt][1] * 0.125f + mb;
            sacc[nt][2] = sacc[nt][2] * 0.125f + ma;
            sacc[nt][3] = sacc[nt][3] * 0.125f + mb;
            tm0 = fmaxf(tm0, fmaxf(sacc[nt][0], sacc[nt][1]));
            tm1 = fmaxf(tm1, fmaxf(sacc[nt][2], sacc[nt][3]));
        }
        tm0 = fmaxf(tm0, __shfl_xor_sync(0xffffffffu, tm0, 1));
        tm0 = fmaxf(tm0, __shfl_xor_sync(0xffffffffu, tm0, 2));
        tm1 = fmaxf(tm1, __shfl_xor_sync(0xffffffffu, tm1, 1));
        tm1 = fmaxf(tm1, __shfl_xor_sync(0xffffffffu, tm1, 2));

        const float mn0 = fmaxf(m0, tm0), mn1 = fmaxf(m1, tm1);
        const float a0 = __expf(m0 - mn0), a1 = __expf(m1 - mn1);
        m0 = mn0; m1 = mn1;

        float rs0 = 0.f, rs1 = 0.f;
        #pragma unroll
        for (int nt = 0; nt < 8; nt++) {
            sacc[nt][0] = __expf(sacc[nt][0] - mn0);
            sacc[nt][1] = __expf(sacc[nt][1] - mn0);
            sacc[nt][2] = __expf(sacc[nt][2] - mn1);
            sacc[nt][3] = __expf(sacc[nt][3] - mn1);
            rs0 += sacc[nt][0] + sacc[nt][1];
            rs1 += sacc[nt][2] + sacc[nt][3];
        }
        rs0 += __shfl_xor_sync(0xffffffffu, rs0, 1);
        rs0 += __shfl_xor_sync(0xffffffffu, rs0, 2);
        rs1 += __shfl_xor_sync(0xffffffffu, rs1, 1);
        rs1 += __shfl_xor_sync(0xffffffffu, rs1, 2);
        l0 = l0 * a0 + rs0;
        l1 = l1 * a1 + rs1;

        uint32_t pa[4][4];
        #pragma unroll
        for (int ks = 0; ks < 4; ks++) {
            pa[ks][0] = packh2(sacc[2 * ks][0],     sacc[2 * ks][1]);
            pa[ks][1] = packh2(sacc[2 * ks][2],     sacc[2 * ks][3]);
            pa[ks][2] = packh2(sacc[2 * ks + 1][0], sacc[2 * ks + 1][1]);
            pa[ks][3] = packh2(sacc[2 * ks + 1][2], sacc[2 * ks + 1][3]);
        }

        #pragma unroll
        for (int nt = 0; nt < 8; nt++) {
            oacc[nt][0] *= a0; oacc[nt][1] *= a0;
            oacc[nt][2] *= a1; oacc[nt][3] *= a1;
        }

        #pragma unroll
        for (int ks = 0; ks < 4; ks++) {
            #pragma unroll
            for (int ng = 0; ng < 4; ng++) {
                const int row = ks * 16 + 8 * (vg & 1) + vi;
                const int cc = ng * 2 + (vg >> 1);
                uint32_t bf[4];
                ldsm_x4_t(bf, vst + row * 128 + (((cc ^ (row & 7))) << 4));
                mma_f16(oacc[ng * 2],     pa[ks], bf);
                mma_f16(oacc[ng * 2 + 1], pa[ks], bf + 2);
            }
        }
        __syncthreads();
    }

    const float inv0 = 1.0f / l0, inv1 = 1.0f / l1;
    const int r0 = qBase + wrow + (lane >> 2);
    __half* Og = attn + (size_t)b * S_ * D_ + h * DK_;
    #pragma unroll
    for (int nt = 0; nt < 8; nt++) {
        const int col = nt * 8 + 2 * (lane & 3);
        *(__half2*)(Og + (size_t)r0 * D_ + col) =
            __floats2half2_rn(oacc[nt][0] * inv0, oacc[nt][1] * inv0);
        *(__half2*)(Og + (size_t)(r0 + 8) * D_ + col) =
            __floats2half2_rn(oacc[nt][2] * inv1, oacc[nt][3] * inv1);
    }
}

// ================= weight transposes -> fp16 =================
__global__ __launch_bounds__(256) void transpose_h_kernel(
    const float* __restrict__ W, __half* __restrict__ Wt, int Kd, int Nd)
{
    __shared__ float t[32][33];
    const int k0 = blockIdx.y * 32, n0 = blockIdx.x * 32;
    const int tx = threadIdx.x & 31, ty = threadIdx.x >> 5;
    #pragma unroll
    for (int i = 0; i < 32; i += 8)
        t[ty + i][tx] = W[(size_t)(k0 + ty + i) * Nd + n0 + tx];
    __syncthreads();
    #pragma unroll
    for (int i = 0; i < 32; i += 8)
        Wt[(size_t)(n0 + ty + i) * Kd + k0 + tx] = __float2half_rn(t[tx][ty + i]);
}

// fused qkv transpose: z selects wq/wk/wv -> rows [z*D, (z+1)*D) of Wt[3D, D]
__global__ __launch_bounds__(256) void transpose_qkv_kernel(
    const float* __restrict__ Wq, const float* __restrict__ Wk,
    const float* __restrict__ Wv,
    const float* __restrict__ bq, const float* __restrict__ bk,
    const float* __restrict__ bv,
    __half* __restrict__ Wt, float* __restrict__ bqkv)
{
    __shared__ float t[32][33];
    const int zz = blockIdx.z;
    const float* W = (zz == 0) ? Wq : (zz == 1) ? Wk : Wv;
    const int k0 = blockIdx.y * 32, n0 = blockIdx.x * 32;
    const int tx = threadIdx.x & 31, ty = threadIdx.x >> 5;
    #pragma unroll
    for (int i = 0; i < 32; i += 8)
        t[ty + i][tx] = W[(size_t)(k0 + ty + i) * D_ + n0 + tx];
    __syncthreads();
    #pragma unroll
    for (int i = 0; i < 32; i += 8)
        Wt[(size_t)(zz * D_ + n0 + ty + i) * D_ + k0 + tx] = __float2half_rn(t[tx][ty + i]);
    if (blockIdx.y == 0 && threadIdx.x < 32 && blockIdx.x * 32 + threadIdx.x < D_) {
        const int n = blockIdx.x * 32 + threadIdx.x;
        const float* bb = (zz == 0) ? bq : (zz == 1) ? bk : bv;
        bqkv[zz * D_ + n] = bb[n];
    }
}

// ================= LayerNorm (ddof=1, /(std+eps)) -> fp16 output =================
__global__ __launch_bounds__(256) void ln_kernel(
    const float* __restrict__ x, const float* __restrict__ w,
    const float* __restrict__ b, __half* __restrict__ y)
{
    __shared__ float red[256];
    const int row = blockIdx.x;
    const int tid = threadIdx.x;
    const float* xr = x + (size_t)row * D_;
    float v0 = xr[tid], v1 = xr[tid + 256], v2 = xr[tid + 512], v3 = xr[tid + 768];

    red[tid] = v0 + v1 + v2 + v3; __syncthreads();
    for (int off = 128; off > 0; off >>= 1) {
        if (tid < off) red[tid] += red[tid + off];
        __syncthreads();
    }
    float mean = red[0] * (1.0f / D_);
    __syncthreads();

    float d0 = v0 - mean, d1 = v1 - mean, d2 = v2 - mean, d3 = v3 - mean;
    red[tid] = d0 * d0 + d1 * d1 + d2 * d2 + d3 * d3; __syncthreads();
    for (int off = 128; off > 0; off >>= 1) {
        if (tid < off) red[tid] += red[tid + off];
        __syncthreads();
    }
    float std1 = sqrtf(red[0] / (float)(D_ - 1));
    float rinv = 1.0f / (std1 + EPS_);

    __half* yr = y + (size_t)row * D_;
    yr[tid]       = __float2half_rn(w[tid]       * d0 * rinv + b[tid]);
    yr[tid + 256] = __float2half_rn(w[tid + 256] * d1 * rinv + b[tid + 256]);
    yr[tid + 512] = __float2half_rn(w[tid + 512] * d2 * rinv + b[tid + 512]);
    yr[tid + 768] = __float2half_rn(w[tid + 768] * d3 * rinv + b[tid + 768]);
}

// ================= host launcher =================
extern "C" void kernel_launch(void* const* d_in, const int* in_sizes, int n_in,
                              void* d_out, int out_size)
{
    const float* x    = (const float*)d_in[0];
    const int*   mask = (const int*)  d_in[1];
    const float* wq   = (const float*)d_in[2];
    const float* bq   = (const float*)d_in[3];
    const float* wk   = (const float*)d_in[4];
    const float* bk   = (const float*)d_in[5];
    const float* wv   = (const float*)d_in[6];
    const float* bv   = (const float*)d_in[7];
    const float* wo   = (const float*)d_in[8];
    const float* bo   = (const float*)d_in[9];
    const float* w1   = (const float*)d_in[10];
    const float* b1   = (const float*)d_in[11];
    const float* w2   = (const float*)d_in[12];
    const float* b2   = (const float*)d_in[13];
    const float* ln1w = (const float*)d_in[14];
    const float* ln1b = (const float*)d_in[15];
    const float* ln2w = (const float*)d_in[16];
    const float* ln2b = (const float*)d_in[17];
    float* out = (float*)d_out;

    __half *xn, *qkv, *attn, *hbuf, *wqkvT, *woT, *w1T, *w2T;
    float *x1, *bqkv;
    cudaGetSymbolAddress((void**)&xn,    g_xn_h);
    cudaGetSymbolAddress((void**)&qkv,   g_qkv_h);
    cudaGetSymbolAddress((void**)&attn,  g_attn_h);
    cudaGetSymbolAddress((void**)&x1,    g_x1);
    cudaGetSymbolAddress((void**)&hbuf,  g_h_h);
    cudaGetSymbolAddress((void**)&wqkvT, g_wqkvT);
    cudaGetSymbolAddress((void**)&bqkv,  g_bqkv);
    cudaGetSymbolAddress((void**)&woT,   g_woT);
    cudaGetSymbolAddress((void**)&w1T,   g_w1T);
    cudaGetSymbolAddress((void**)&w2T,   g_w2T);

    auto kQKV  = hgemm<true, false, false, true>;   // half out (feeds flash)
    auto kRES  = hgemm<true, false, true,  false>;  // float out + residual
    auto kFFN1 = hgemm<true, true,  false, true>;   // half out (feeds FFN2)

    cudaFuncSetAttribute(kQKV,  cudaFuncAttributeMaxDynamicSharedMemorySize, HG_SMEM_BYTES);
    cudaFuncSetAttribute(kRES,  cudaFuncAttributeMaxDynamicSharedMemorySize, HG_SMEM_BYTES);
    cudaFuncSetAttribute(kFFN1, cudaFuncAttributeMaxDynamicSharedMemorySize, HG_SMEM_BYTES);
    cudaFuncSetAttribute(flash_h_kernel, cudaFuncAttributeMaxDynamicSharedMemorySize, FA_SMEM_BYTES);

    // weight transposes (fp16): fused qkv in one launch
    {
        dim3 gQ(D_ / 32, D_ / 32, 3);
        transpose_qkv_kernel<<<gQ, 256>>>(wq, wk, wv, bq, bk, bv, wqkvT, bqkv);
        dim3 gT(D_ / 32, D_ / 32);
        transpose_h_kernel<<<gT, 256>>>(wo, woT, D_, D_);
        dim3 gT1(DFF_ / 32, D_ / 32);
        transpose_h_kernel<<<gT1, 256>>>(w1, w1T, D_, DFF_);
        dim3 gT2(D_ / 32, DFF_ / 32);
        transpose_h_kernel<<<gT2, 256>>>(w2, w2T, DFF_, D_);
    }

    // 1) LN1 -> xn (half)
    ln_kernel<<<NTOK, 256>>>(x, ln1w, ln1b, xn);

    // 2) fused QKV projection: [8192,1024] @ [1024,3072] -> half [8192,3072]
    dim3 gQKV(3 * D_ / 128, NTOK / 256);
    kQKV<<<gQKV, 256, HG_SMEM_BYTES>>>(xn, wqkvT, bqkv, nullptr, qkv,
                                       NTOK, 3 * D_, D_, D_, D_, 3 * D_);

    // 3) fp16 flash attention -> attn (half)
    dim3 gFA(S_ / 128, NBH);
    flash_h_kernel<<<gFA, 256, FA_SMEM_BYTES>>>(qkv, mask, attn);

    // 4) x1 = x + attn @ wo + bo  (float)
    dim3 gProj(D_ / 128, NTOK / 256);
    kRES<<<gProj, 256, HG_SMEM_BYTES>>>(attn, woT, bo, x, x1, NTOK, D_, D_, D_, D_, D_);

    // 5) LN2 -> xn (half)
    ln_kernel<<<NTOK, 256>>>(x1, ln2w, ln2b, xn);

    // 6) h = relu(xn @ w1 + b1) -> half
    dim3 gF1(DFF_ / 128, NTOK / 256);
    kFFN1<<<gF1, 256, HG_SMEM_BYTES>>>(xn, w1T, b1, nullptr, hbuf, NTOK, DFF_, D_, D_, D_, DFF_);

    // 7) out = x1 + h @ w2 + b2  (float)
    kRES<<<gProj, 256, HG_SMEM_BYTES>>>(hbuf, w2T, b2, x1, out, NTOK, D_, DFF_, DFF_, DFF_, D_);
}